// round 14
// baseline (speedup 1.0000x reference)
#include <cuda_runtime.h>
#include <math.h>

// Problem constants
#define B   256
#define L   512
#define I   32
#define H   16
#define G   64            // 4*H gates
#define NT  511           // number of increments
#define SIGD 4368         // H + H^2 + H^3
#define O   10

// Scratch (device global; no allocation allowed)
static __device__ float g_xw[B * L * G];        // per-batch input projection
                                                // (i,f,o gate rows pre-scaled by 0.5)

// Dynamic shared memory layout (bytes)
#define SM_DS0   0
#define SM_DS1   32768
#define SM_XSH   65536          // 128*33*4 = 16896
#define SM_WS    82432          // 32*65*4  = 8320
#define SM_BS    90752          // 256
#define SM_HSM   91008          // 2 warps * 2 bufs * 16 * 4 = 512
#define SM_RED   91520          // 8*10*4 = 320
#define SMEM_TOTAL 91840

// ---------------------------------------------------------------------------
// Hardware MUFU.TANH. Pre-scaled preactivations make sigmoid = fma(tanh,.5,.5).
// ---------------------------------------------------------------------------
__device__ __forceinline__ float tanh_hw(float x) {
    float y; asm("tanh.approx.f32 %0, %1;" : "=f"(y) : "f"(x)); return y;
}

// ---------------------------------------------------------------------------
// Packed fp32x2 helpers (Blackwell FFMA2 via PTX) — sig phase only
// ---------------------------------------------------------------------------
typedef unsigned long long u64t;
__device__ __forceinline__ u64t pack2_(float lo, float hi) {
    u64t r; asm("mov.b64 %0, {%1, %2};" : "=l"(r) : "f"(lo), "f"(hi)); return r;
}
__device__ __forceinline__ void unpack2_(u64t v, float& lo, float& hi) {
    asm("mov.b64 {%0, %1}, %2;" : "=f"(lo), "=f"(hi) : "l"(v));
}
__device__ __forceinline__ u64t ffma2_(u64t a, u64t b, u64t c) {
    u64t d; asm("fma.rn.f32x2 %0, %1, %2, %3;" : "=l"(d) : "l"(a), "l"(b), "l"(c));
    return d;
}

__device__ __forceinline__ void barA() {           // warps 0-7 internal barrier
    asm volatile("bar.sync 1, 256;" ::: "memory");
}
__device__ __forceinline__ void bar_wait(int id) { // HW-blocking wait (no issue)
    asm volatile("bar.sync %0, 288;" :: "r"(id) : "memory");
}
__device__ __forceinline__ void bar_post(int id) { // non-blocking arrive
    asm volatile("bar.arrive %0, 288;" :: "r"(id) : "memory");
}

// gate-row scale: i(0-15), f(16-31), o(48-63) -> 0.5 ; g(32-47) -> 1.0
__device__ __forceinline__ float gscale(int g) {
    return (g >= 32 && g < 48) ? 1.0f : 0.5f;
}

// ---------------------------------------------------------------------------
// FUSED kernel: ONE BLOCK PER SM (128 blocks, 320 thr = 10 warps), TWO batches
// per block. Warps 8 & 9 run the two LSTM chains on SMSP 0 & 1 (never sharing
// a scheduler — the R13 wall was two co-resident blocks' chains both on
// SMSP 0). Warps 0-7 produce xw for both batches, then consume both sig scans.
// Barriers: id1 = warps0-7 internal; ids 2-5 = xw halves (b0h1,b0h2,b1h1,b1h2);
// ids 6-9 / 10-13 = sig chunks of batch0 / batch1. All producer/consumer pairs
// total 288 arrivals.
// ---------------------------------------------------------------------------
__global__ void __launch_bounds__(320) fused_kernel(const float* __restrict__ X,
                                                    const float* __restrict__ Wih,
                                                    const float* __restrict__ Whh,
                                                    const float* __restrict__ bih,
                                                    const float* __restrict__ bhh,
                                                    const float* __restrict__ fcw,
                                                    const float* __restrict__ fcb,
                                                    float* __restrict__ out) {
    extern __shared__ __align__(16) char smem_raw[];
    float* ds0 = reinterpret_cast<float*>(smem_raw + SM_DS0);
    float* ds1 = reinterpret_cast<float*>(smem_raw + SM_DS1);
    float* Xsh = reinterpret_cast<float*>(smem_raw + SM_XSH);
    float* Ws  = reinterpret_cast<float*>(smem_raw + SM_WS);
    float* bs  = reinterpret_cast<float*>(smem_raw + SM_BS);
    float* hsm = reinterpret_cast<float*>(smem_raw + SM_HSM);  // [lw][buf][16]
    float* red = reinterpret_cast<float*>(smem_raw + SM_RED);  // [8][O]

    int tid  = threadIdx.x;
    int lane = tid & 31;
    int warp = tid >> 5;
    int b0   = blockIdx.x * 2;                  // batches b0, b0+1

    if (warp < 8) {
        // ============ Phase A: xw for BOTH batches (8 tiles of 128 rows) ====
        for (int i = tid; i < 2048; i += 256) {    // W_ih transpose + scale
            int g = i >> 5, k = i & 31;
            Ws[k * 65 + g] = Wih[i] * gscale(g);
        }
        if (tid < 64) bs[tid] = (bih[tid] + bhh[tid]) * gscale(tid);

        int tg = tid & 15;
        int tb = tid >> 4;

        // tile order: (b,t): (0,0) post2 | (1,0) post4 | (0,1)(0,2)(0,3) post3
        //             | (1,1)(1,2)(1,3) post5
        const int tb_b[8] = {0, 1, 0, 0, 0, 1, 1, 1};
        const int tb_t[8] = {0, 0, 1, 2, 3, 1, 2, 3};
        const int tb_post[8] = {2, 4, -1, -1, 3, -1, -1, 5};

        for (int q = 0; q < 8; q++) {
            int bat  = b0 + tb_b[q];
            int tile = tb_t[q];
            float* xwb = g_xw + (size_t)bat * (L * G);

            barA();
            for (int i = tid; i < 4096; i += 256) {
                int r = i >> 5, k = i & 31;
                Xsh[r * 33 + k] = X[((size_t)bat * L + tile * 128) * I + i];
            }
            barA();

#pragma unroll
            for (int s = 0; s < 2; s++) {
                float acc[4][4];
#pragma unroll
                for (int bi = 0; bi < 4; bi++)
#pragma unroll
                    for (int gi = 0; gi < 4; gi++)
                        acc[bi][gi] = bs[tg * 4 + gi];

#pragma unroll 8
                for (int k = 0; k < I; k++) {
                    float xv[4], wv[4];
#pragma unroll
                    for (int bi = 0; bi < 4; bi++)
                        xv[bi] = Xsh[(s * 64 + tb * 4 + bi) * 33 + k];
#pragma unroll
                    for (int gi = 0; gi < 4; gi++) wv[gi] = Ws[k * 65 + tg * 4 + gi];
#pragma unroll
                    for (int bi = 0; bi < 4; bi++)
#pragma unroll
                        for (int gi = 0; gi < 4; gi++)
                            acc[bi][gi] = fmaf(xv[bi], wv[gi], acc[bi][gi]);
                }

#pragma unroll
                for (int bi = 0; bi < 4; bi++) {
                    int row = tile * 128 + s * 64 + tb * 4 + bi;
                    float4 v = make_float4(acc[bi][0], acc[bi][1], acc[bi][2], acc[bi][3]);
                    *reinterpret_cast<float4*>(xwb + (size_t)row * G + tg * 4) = v;
                }
            }
            if (tb_post[q] >= 0) {
                __threadfence_block();
                bar_post(tb_post[q]);
            }
        }

        // ============ Phase C: sig scans for batch0 then batch1 =============
        int a  = tid >> 4;
        int bb = tid & 15;

        for (int bsel = 0; bsel < 2; bsel++) {
            const float* ds = bsel ? ds1 : ds0;
            int wait_base = 6 + bsel * 4;

            float S1h = 0.f, S2 = 0.f;             // S1h = S1/2 (exact scaling)
            u64t S3p[8];
#pragma unroll
            for (int j = 0; j < 8; j++) S3p[j] = 0ull;

            for (int k = 0; k < 4; k++) {
                bar_wait(wait_base + k);           // HW-parked until chunk ready
                int tend = (k < 3) ? (k + 1) * 128 : NT;

#pragma unroll 2
                for (int t = k * 128; t < tend; t++) {
                    const float* dr = ds + t * H;
                    ulonglong2 p0 = *reinterpret_cast<const ulonglong2*>(dr);
                    ulonglong2 p1 = *reinterpret_cast<const ulonglong2*>(dr + 4);
                    ulonglong2 p2 = *reinterpret_cast<const ulonglong2*>(dr + 8);
                    ulonglong2 p3 = *reinterpret_cast<const ulonglong2*>(dr + 12);
                    float da = dr[a];
                    float db = dr[bb];

                    float m1   = da * db;
                    float db2  = db + db;
                    float coef = fmaf(S1h, db, fmaf(m1, (1.f / 6.f), S2));
                    u64t cp = pack2_(coef, coef);

                    S3p[0] = ffma2_(cp, p0.x, S3p[0]);
                    S3p[1] = ffma2_(cp, p0.y, S3p[1]);
                    S3p[2] = ffma2_(cp, p1.x, S3p[2]);
                    S3p[3] = ffma2_(cp, p1.y, S3p[3]);
                    S3p[4] = ffma2_(cp, p2.x, S3p[4]);
                    S3p[5] = ffma2_(cp, p2.y, S3p[5]);
                    S3p[6] = ffma2_(cp, p3.x, S3p[6]);
                    S3p[7] = ffma2_(cp, p3.y, S3p[7]);

                    S2  = fmaf(S1h, db2, fmaf(0.5f, m1, S2));
                    S1h = fmaf(0.5f, da, S1h);
                }
            }

            // ---- fused FC for this batch ----
            float S3[16];
#pragma unroll
            for (int j = 0; j < 8; j++) unpack2_(S3p[j], S3[2 * j], S3[2 * j + 1]);
            float S1 = S1h + S1h;

            float part[O];
#pragma unroll
            for (int o = 0; o < O; o++) {
                const float* wr = fcw + (size_t)o * SIGD;
                float acc = S2 * __ldg(wr + H + tid);              // level-2
                if (bb == 0) acc = fmaf(S1, __ldg(wr + a), acc);   // level-1
                const float4* w4 = reinterpret_cast<const float4*>(wr + H + H * H + tid * 16);
#pragma unroll
                for (int j = 0; j < 4; j++) {
                    float4 w = __ldg(w4 + j);
                    acc = fmaf(S3[4 * j + 0], w.x, acc);
                    acc = fmaf(S3[4 * j + 1], w.y, acc);
                    acc = fmaf(S3[4 * j + 2], w.z, acc);
                    acc = fmaf(S3[4 * j + 3], w.w, acc);
                }
                part[o] = acc;
            }

#pragma unroll
            for (int off = 16; off > 0; off >>= 1)
#pragma unroll
                for (int o = 0; o < O; o++)
                    part[o] += __shfl_down_sync(0xffffffffu, part[o], off);
            if (lane == 0)
#pragma unroll
                for (int o = 0; o < O; o++) red[warp * O + o] = part[o];
            barA();
            if (tid < O) {
                float v = fcb[tid];
#pragma unroll
                for (int w = 0; w < 8; w++) v += red[w * O + tid];
                out[(b0 + bsel) * O + tid] = v;
            }
            barA();                                // red reusable for next batch
        }
    } else {
        // ============ Phase B: LSTM chains (warps 8 & 9) ====================
        int lw  = warp - 8;                        // 0 or 1
        int bat = b0 + lw;
        float* dsp = lw ? ds1 : ds0;
        float* hs  = hsm + lw * 32;                // [buf][16]
        int xw_id0 = 2 + lw * 2;                   // 2 / 4
        int xw_id1 = 3 + lw * 2;                   // 3 / 5
        int sig_base = 6 + lw * 4;                 // 6 / 10

        // lane l: rows l (i/f, x0.5) and l+32 (g x1 / o x0.5)
        float sc1 = (lane < 16) ? 1.0f : 0.5f;
        float w0[H], w1[H];
#pragma unroll
        for (int j = 0; j < H; j++) {
            w0[j] = 0.5f * __ldg(Whh + lane * H + j);
            w1[j] = sc1  * __ldg(Whh + (lane + 32) * H + j);
        }
        float h[H];
#pragma unroll
        for (int j = 0; j < H; j++) h[j] = 0.f;
        float c = 0.f, hprev = 0.f;

        const float* xp = g_xw + (size_t)bat * (L * G) + lane;

        bar_wait(xw_id0);                          // rows 0-127 ready

        float bx0[4], bx1[4];
#pragma unroll
        for (int k = 0; k < 4; k++) { bx0[k] = xp[k * G]; bx1[k] = xp[k * G + 32]; }

#pragma unroll 4
        for (int t = 0; t < L; t++) {
            if (t == 96) bar_wait(xw_id1);         // rows 128-511 (needed @124)
            if ((t & 127) == 0 && t) {
                __threadfence_block();
                bar_post(sig_base + (t >> 7) - 1); // sig chunks 0..2
            }

            int slot = t & 3;
            float a0 = bx0[slot], a1 = bx1[slot];
            if (t + 4 < L) { bx0[slot] = xp[(t + 4) * G]; bx1[slot] = xp[(t + 4) * G + 32]; }

            float q0 = 0.f, q1 = 0.f;
#pragma unroll
            for (int j = 0; j < 8; j++) {
                a0 = fmaf(h[j],     w0[j],     a0);
                q0 = fmaf(h[j + 8], w0[j + 8], q0);
                a1 = fmaf(h[j],     w1[j],     a1);
                q1 = fmaf(h[j + 8], w1[j + 8], q1);
            }
            a0 += q0; a1 += q1;
            // a0 = (i|f preact)/2 ; a1 = g preact (<16) | (o preact)/2 (>=16)

            float s0   = tanh_hw(a0);
            float sig0 = fmaf(s0, 0.5f, 0.5f);     // si (<16) / sf (>=16)
            float t1   = tanh_hw(a1);              // tg (<16) / tanh(o/2) (>=16)
            float soq  = fmaf(t1, 0.5f, 0.5f);     // so (valid on lanes>=16)

            float sf = __shfl_down_sync(0xffffffffu, sig0, 16);
            float so = __shfl_down_sync(0xffffffffu, soq, 16);

            c = fmaf(sf, c, sig0 * t1);            // lanes<16 valid
            float hn = so * tanh_hw(c);

            int buf = t & 1;
            if (lane < H) {
                hs[buf * 16 + lane] = hn;
                if (t) dsp[(t - 1) * H + lane] = hn - hprev;
                hprev = hn;
            }
            __syncwarp();
#pragma unroll
            for (int j = 0; j < H; j += 4) {
                float4 v = *reinterpret_cast<const float4*>(&hs[buf * 16 + j]);
                h[j] = v.x; h[j + 1] = v.y; h[j + 2] = v.z; h[j + 3] = v.w;
            }
        }
        __threadfence_block();
        bar_post(sig_base + 3);                    // final sig chunk (384..510)
    }

    __syncthreads();                               // all 10 warps (barrier 0)
}

// ---------------------------------------------------------------------------
extern "C" void kernel_launch(void* const* d_in, const int* in_sizes, int n_in,
                              void* d_out, int out_size) {
    const float* X   = (const float*)d_in[0];
    const float* Wih = (const float*)d_in[1];
    const float* Whh = (const float*)d_in[2];
    const float* bih = (const float*)d_in[3];
    const float* bhh = (const float*)d_in[4];
    const float* fcw = (const float*)d_in[5];
    const float* fcb = (const float*)d_in[6];
    float* out = (float*)d_out;

    cudaFuncSetAttribute(fused_kernel,
                         cudaFuncAttributeMaxDynamicSharedMemorySize, SMEM_TOTAL);
    fused_kernel<<<B / 2, 320, SMEM_TOTAL>>>(X, Wih, Whh, bih, bhh, fcw, fcb, out);
}